// round 2
// baseline (speedup 1.0000x reference)
#include <cuda_runtime.h>
#include <cuda_bf16.h>
#include <cstdint>

#define HW 65536
#define NB 8

// ---- scratch (__device__ globals; allocation is forbidden) ----
__device__ float g_sum[512], g_sq[512], g_pool[512], g_s2[512], g_q2[512];
__device__ float g_b1f[NB*128], g_b3f[NB*128];
__device__ __nv_bfloat16 g_w1f[NB*128*64], g_w3f[NB*128*64], g_w2f[NB*64*64], g_w4h[64*64];
__device__ __nv_bfloat16 g_t[(size_t)NB*128*HW];   // pw1 output (128 MB)
__device__ __nv_bfloat16 g_y[(size_t)NB*64*HW];    // gate output (64 MB)

__device__ __forceinline__ float warpsum(float v){
#pragma unroll
  for(int o=16;o>0;o>>=1) v += __shfl_down_sync(0xffffffffu, v, o);
  return v;
}

__device__ __forceinline__ void mma_bf16(float& d0,float& d1,float& d2,float& d3,
    uint32_t a0,uint32_t a1,uint32_t a2,uint32_t a3,uint32_t b0,uint32_t b1){
  asm volatile("mma.sync.aligned.m16n8k16.row.col.f32.bf16.bf16.f32 "
    "{%0,%1,%2,%3},{%4,%5,%6,%7},{%8,%9},{%0,%1,%2,%3};"
    : "+f"(d0),"+f"(d1),"+f"(d2),"+f"(d3)
    : "r"(a0),"r"(a1),"r"(a2),"r"(a3),"r"(b0),"r"(b1));
}

// load A fragments (4 k-steps) from row-major bf16 [rows][64]
__device__ __forceinline__ void loadA(uint32_t A[4][4], const __nv_bfloat16* wf,
                                      int m0,int grp,int t4){
#pragma unroll
  for(int k=0;k<4;k++){
    int c0=k*16+2*t4;
    A[k][0]=*(const uint32_t*)(wf+(m0+grp)*64+c0);
    A[k][1]=*(const uint32_t*)(wf+(m0+grp+8)*64+c0);
    A[k][2]=*(const uint32_t*)(wf+(m0+grp)*64+c0+8);
    A[k][3]=*(const uint32_t*)(wf+(m0+grp+8)*64+c0+8);
  }
}

// ---------------- K1: per-(n,c) sum / sumsq of x ----------------
__global__ __launch_bounds__(256) void k1(const float* __restrict__ x){
  int nc=blockIdx.x, tid=threadIdx.x;
  const float4* p=(const float4*)(x+(size_t)nc*HW);
  float s=0.f,q=0.f;
  for(int i=tid;i<HW/4;i+=256){
    float4 v=p[i];
    s+=(v.x+v.y)+(v.z+v.w);
    q+=v.x*v.x+v.y*v.y+v.z*v.z+v.w*v.w;
  }
  s=warpsum(s); q=warpsum(q);
  __shared__ float rs[8],rq[8];
  if((tid&31)==0){rs[tid>>5]=s;rq[tid>>5]=q;}
  __syncthreads();
  if(tid==0){
    float S=0,Q=0;
#pragma unroll
    for(int i=0;i<8;i++){S+=rs[i];Q+=rq[i];}
    g_sum[nc]=S; g_sq[nc]=Q;
  }
}

// ---------------- K2: fold ln1 into pw1; convert pw4; zero pool ----------------
__global__ void k2(const float* __restrict__ ln1w,const float* __restrict__ ln1b,
                   const float* __restrict__ pw1w,const float* __restrict__ pw1b,
                   const float* __restrict__ pw4w){
  int n=blockIdx.x, o=threadIdx.x; // 128 threads
  __shared__ float a[64], cc[64];
  if(o<64){
    float mean=g_sum[n*64+o]*(1.f/HW);
    float var =g_sq[n*64+o]*(1.f/HW)-mean*mean;
    float ai=ln1w[o]*rsqrtf(var+1e-6f);
    a[o]=ai; cc[o]=ln1b[o]-mean*ai;
    g_pool[n*64+o]=0.f;
  }
  __syncthreads();
  float bacc=pw1b[o];
#pragma unroll 8
  for(int c=0;c<64;c++){
    float w=pw1w[o*64+c];
    bacc+=w*cc[c];
    g_w1f[(n*128+o)*64+c]=__float2bfloat16(w*a[c]);
  }
  g_b1f[n*128+o]=bacc;
  if(n==0&&o<64){
    for(int c=0;c<64;c++) g_w4h[o*64+c]=__float2bfloat16(pw4w[o*64+c]);
  }
}

// ---------------- K3a: pw1 GEMM (folded LN1), 1 image row / block ----------------
__global__ __launch_bounds__(256) void k3a(const float* __restrict__ x){
  int row=blockIdx.x, n=blockIdx.y, tid=threadIdx.x;
  __shared__ __nv_bfloat16 xs[256*72];
  const float* xp=x+(size_t)n*64*HW+row*256;
#pragma unroll 4
  for(int c=0;c<64;c++) xs[tid*72+c]=__float2bfloat16(xp[(size_t)c*HW+tid]);
  __syncthreads();
  int wid=tid>>5, lane=tid&31, grp=lane>>2, t4=lane&3, m0=wid*16;
  const __nv_bfloat16* wf=g_w1f+(size_t)n*128*64;
  uint32_t A[4][4]; loadA(A,wf,m0,grp,t4);
  float bv0=g_b1f[n*128+m0+grp], bv8=g_b1f[n*128+m0+grp+8];
  __nv_bfloat16* tp=g_t+(size_t)n*128*HW+row*256;
  for(int nt=0;nt<32;nt++){
    int p0=nt*8;
    const __nv_bfloat16* bs=xs+(p0+grp)*72+2*t4;
    float d0=0,d1=0,d2=0,d3=0;
#pragma unroll
    for(int k=0;k<4;k++){
      uint32_t b0=*(const uint32_t*)(bs+k*16), b1=*(const uint32_t*)(bs+k*16+8);
      mma_bf16(d0,d1,d2,d3,A[k][0],A[k][1],A[k][2],A[k][3],b0,b1);
    }
    int px=p0+2*t4;
    *(__nv_bfloat162*)(tp+(size_t)(m0+grp)*HW+px)  =__floats2bfloat162_rn(d0+bv0,d1+bv0);
    *(__nv_bfloat162*)(tp+(size_t)(m0+grp+8)*HW+px)=__floats2bfloat162_rn(d2+bv8,d3+bv8);
  }
}

// ---------------- K3b: depthwise 3x3 + gate + pool partials ----------------
__global__ __launch_bounds__(256) void k3b(const float* __restrict__ dww,
                                           const float* __restrict__ dwb){
  int h=blockIdx.x, n=blockIdx.y, tid=threadIdx.x;
  __shared__ float ws[1152], dbs[128], st[6][264], ssum[64];
  for(int i=tid;i<1152;i+=256) ws[i]=dww[i];
  if(tid<128) dbs[tid]=dwb[tid];
  if(tid<64) ssum[tid]=0.f;
  const __nv_bfloat16* tb=g_t+(size_t)n*128*HW;
  __nv_bfloat16* yb=g_y+(size_t)n*64*HW+h*256;
  int w=tid, lane=tid&31;
  for(int c=0;c<64;c++){
    __syncthreads();
    for(int i=tid;i<6*258;i+=256){
      int seg=i/258, col=i-seg*258-1;
      int r=h-1+(seg<3?seg:seg-3);
      int ch=(seg<3)?c:c+64;
      float v=0.f;
      if((unsigned)r<256u&&(unsigned)col<256u)
        v=__bfloat162float(tb[(size_t)ch*HW+r*256+col]);
      st[seg][col+1]=v;
    }
    __syncthreads();
    const float* wA=ws+c*9; const float* wB=ws+(c+64)*9;
    float a=dbs[c], b=dbs[c+64];
#pragma unroll
    for(int dr=0;dr<3;dr++)
#pragma unroll
      for(int dc=0;dc<3;dc++){
        a+=wA[dr*3+dc]*st[dr][w+dc];
        b+=wB[dr*3+dc]*st[3+dr][w+dc];
      }
    float y=a*b;
    yb[(size_t)c*HW+w]=__float2bfloat16(y);
    float t=warpsum(y);
    if(lane==0) atomicAdd(&ssum[c],t);
  }
  __syncthreads();
  if(tid<64) atomicAdd(&g_pool[n*64+tid],ssum[tid]);
}

// ---------------- K4: SCA fold into pw2; zero ln2 stats ----------------
__global__ void k4(const float* __restrict__ scaw,const float* __restrict__ scab,
                   const float* __restrict__ pw2w){
  int n=blockIdx.x, o=threadIdx.x; // 64 threads
  __shared__ float v[64];
  float s=scab[o];
  for(int c=0;c<64;c++) s+=scaw[o*64+c]*(g_pool[n*64+c]*(1.f/HW));
  v[o]=1.f/(1.f+expf(-s));
  g_s2[n*64+o]=0.f; g_q2[n*64+o]=0.f;
  __syncthreads();
  for(int c=0;c<64;c++) g_w2f[(n*64+o)*64+c]=__float2bfloat16(pw2w[o*64+c]*v[c]);
}

// ---------------- K5: pw2 GEMM + residual1 + ln2 stats partials ----------------
__global__ __launch_bounds__(256) void k5(const float* __restrict__ x,
                                          const float* __restrict__ pw2b,
                                          const float* __restrict__ beta1,
                                          float* __restrict__ out){
  int row=blockIdx.x, n=blockIdx.y, tid=threadIdx.x;
  __shared__ __nv_bfloat16 xs[256*72];
  __shared__ float ss[64], sq[64];
  if(tid<64){ss[tid]=0.f;sq[tid]=0.f;}
  const __nv_bfloat16* yp=g_y+(size_t)n*64*HW+row*256;
  for(int i=tid;i<64*256;i+=256){int c=i>>8,p=i&255; xs[p*72+c]=yp[(size_t)c*HW+p];}
  __syncthreads();
  int wid=tid>>5, lane=tid&31, grp=lane>>2, t4=lane&3;
  int m0=(wid&3)*16, ph=(wid>>2)*128;
  const __nv_bfloat16* wf=g_w2f+n*64*64;
  uint32_t A[4][4]; loadA(A,wf,m0,grp,t4);
  int cA=m0+grp, cB=m0+grp+8;
  float biA=pw2b[cA],biB=pw2b[cB],beA=beta1[cA],beB=beta1[cB];
  const float* xpA=x+(size_t)(n*64+cA)*HW+row*256;
  const float* xpB=x+(size_t)(n*64+cB)*HW+row*256;
  float* opA=out+(size_t)(n*64+cA)*HW+row*256;
  float* opB=out+(size_t)(n*64+cB)*HW+row*256;
  float sA=0,qA=0,sB=0,qB=0;
  for(int nt=0;nt<16;nt++){
    int p0=ph+nt*8;
    const __nv_bfloat16* bs=xs+(p0+grp)*72+2*t4;
    float d0=0,d1=0,d2=0,d3=0;
#pragma unroll
    for(int k=0;k<4;k++){
      uint32_t b0=*(const uint32_t*)(bs+k*16), b1=*(const uint32_t*)(bs+k*16+8);
      mma_bf16(d0,d1,d2,d3,A[k][0],A[k][1],A[k][2],A[k][3],b0,b1);
    }
    int px=p0+2*t4;
    float2 xa=*(const float2*)(xpA+px), xb=*(const float2*)(xpB+px);
    float o0=xa.x+beA*(d0+biA), o1=xa.y+beA*(d1+biA);
    float o2=xb.x+beB*(d2+biB), o3=xb.y+beB*(d3+biB);
    *(float2*)(opA+px)=make_float2(o0,o1);
    *(float2*)(opB+px)=make_float2(o2,o3);
    sA+=o0+o1; qA+=o0*o0+o1*o1; sB+=o2+o3; qB+=o2*o2+o3*o3;
  }
  sA+=__shfl_down_sync(0xffffffffu,sA,2); sA+=__shfl_down_sync(0xffffffffu,sA,1);
  qA+=__shfl_down_sync(0xffffffffu,qA,2); qA+=__shfl_down_sync(0xffffffffu,qA,1);
  sB+=__shfl_down_sync(0xffffffffu,sB,2); sB+=__shfl_down_sync(0xffffffffu,sB,1);
  qB+=__shfl_down_sync(0xffffffffu,qB,2); qB+=__shfl_down_sync(0xffffffffu,qB,1);
  if(t4==0){
    atomicAdd(&ss[cA],sA); atomicAdd(&sq[cA],qA);
    atomicAdd(&ss[cB],sB); atomicAdd(&sq[cB],qB);
  }
  __syncthreads();
  if(tid<64){atomicAdd(&g_s2[n*64+tid],ss[tid]); atomicAdd(&g_q2[n*64+tid],sq[tid]);}
}

// ---------------- K6: fold ln2 into pw3 ----------------
__global__ void k6(const float* __restrict__ ln2w,const float* __restrict__ ln2b,
                   const float* __restrict__ pw3w,const float* __restrict__ pw3b){
  int n=blockIdx.x, o=threadIdx.x; // 128
  __shared__ float a[64], cc[64];
  if(o<64){
    float mean=g_s2[n*64+o]*(1.f/HW);
    float var =g_q2[n*64+o]*(1.f/HW)-mean*mean;
    float ai=ln2w[o]*rsqrtf(var+1e-6f);
    a[o]=ai; cc[o]=ln2b[o]-mean*ai;
  }
  __syncthreads();
  float bacc=pw3b[o];
#pragma unroll 8
  for(int c=0;c<64;c++){
    float w=pw3w[o*64+c];
    bacc+=w*cc[c];
    g_w3f[(n*128+o)*64+c]=__float2bfloat16(w*a[c]);
  }
  g_b3f[n*128+o]=bacc;
}

// ---------------- K7: pw3 + gate + pw4 + residual2 (in-place on d_out) ----------------
__global__ __launch_bounds__(256) void k7(const float* __restrict__ pw4b,
                                          const float* __restrict__ beta2,
                                          float* __restrict__ out){
  extern __shared__ __nv_bfloat16 sm7[];
  __nv_bfloat16* xs=sm7;            // [128][72]
  __nv_bfloat16* ts=sm7+128*72;     // [128][136]
  int blk=blockIdx.x, n=blockIdx.y, tid=threadIdx.x;
  int base=blk*128;
  const float* xp=out+(size_t)n*64*HW+base;
  for(int i=tid;i<64*128;i+=256){int c=i>>7,p=i&127; xs[p*72+c]=__float2bfloat16(xp[(size_t)c*HW+p]);}
  __syncthreads();
  int wid=tid>>5, lane=tid&31, grp=lane>>2, t4=lane&3;
  { // stage 1: t[128ch] = W3f @ x
    int m0=wid*16;
    const __nv_bfloat16* wf=g_w3f+(size_t)n*128*64;
    uint32_t A[4][4]; loadA(A,wf,m0,grp,t4);
    float bv0=g_b3f[n*128+m0+grp], bv8=g_b3f[n*128+m0+grp+8];
    for(int nt=0;nt<16;nt++){
      int p0=nt*8;
      const __nv_bfloat16* bs=xs+(p0+grp)*72+2*t4;
      float d0=0,d1=0,d2=0,d3=0;
#pragma unroll
      for(int k=0;k<4;k++){
        uint32_t b0=*(const uint32_t*)(bs+k*16), b1=*(const uint32_t*)(bs+k*16+8);
        mma_bf16(d0,d1,d2,d3,A[k][0],A[k][1],A[k][2],A[k][3],b0,b1);
      }
      int px=p0+2*t4;
      ts[px*136+m0+grp]      =__float2bfloat16(d0+bv0);
      ts[(px+1)*136+m0+grp]  =__float2bfloat16(d1+bv0);
      ts[px*136+m0+grp+8]    =__float2bfloat16(d2+bv8);
      ts[(px+1)*136+m0+grp+8]=__float2bfloat16(d3+bv8);
    }
  }
  __syncthreads();
  { // stage 2: z = W4 @ (t[0:64]*t[64:128]); out = x + beta2*(z+b4)
    int m0=(wid&3)*16, ph=(wid>>2)*64;
    uint32_t A[4][4]; loadA(A,g_w4h,m0,grp,t4);
    int cA=m0+grp, cB=m0+grp+8;
    float biA=pw4b[cA],biB=pw4b[cB],beA=beta2[cA],beB=beta2[cB];
    const float* rpA=out+(size_t)(n*64+cA)*HW+base;
    const float* rpB=out+(size_t)(n*64+cB)*HW+base;
    float* opA=out+(size_t)(n*64+cA)*HW+base;
    float* opB=out+(size_t)(n*64+cB)*HW+base;
    for(int nt=0;nt<8;nt++){
      int p0=ph+nt*8;
      const __nv_bfloat16* bs=ts+(p0+grp)*136+2*t4;
      float d0=0,d1=0,d2=0,d3=0;
#pragma unroll
      for(int k=0;k<4;k++){
        __nv_bfloat162 u1=*(const __nv_bfloat162*)(bs+k*16);
        __nv_bfloat162 u2=*(const __nv_bfloat162*)(bs+k*16+64);
        __nv_bfloat162 v1=*(const __nv_bfloat162*)(bs+k*16+8);
        __nv_bfloat162 v2=*(const __nv_bfloat162*)(bs+k*16+72);
        __nv_bfloat162 bb0=__hmul2(u1,u2), bb1=__hmul2(v1,v2);
        mma_bf16(d0,d1,d2,d3,A[k][0],A[k][1],A[k][2],A[k][3],
                 *(uint32_t*)&bb0,*(uint32_t*)&bb1);
      }
      int px=p0+2*t4;
      float2 xa=*(const float2*)(rpA+px), xb=*(const float2*)(rpB+px);
      float o0=xa.x+beA*(d0+biA), o1=xa.y+beA*(d1+biA);
      float o2=xb.x+beB*(d2+biB), o3=xb.y+beB*(d3+biB);
      *(float2*)(opA+px)=make_float2(o0,o1);
      *(float2*)(opB+px)=make_float2(o2,o3);
    }
  }
}

extern "C" void kernel_launch(void* const* d_in, const int* in_sizes, int n_in,
                              void* d_out, int out_size){
  const float* x    =(const float*)d_in[0];
  const float* ln1w =(const float*)d_in[1];
  const float* ln1b =(const float*)d_in[2];
  const float* pw1w =(const float*)d_in[3];
  const float* pw1b =(const float*)d_in[4];
  const float* dww  =(const float*)d_in[5];
  const float* dwb  =(const float*)d_in[6];
  const float* scaw =(const float*)d_in[7];
  const float* scab =(const float*)d_in[8];
  const float* pw2w =(const float*)d_in[9];
  const float* pw2b =(const float*)d_in[10];
  const float* ln2w =(const float*)d_in[11];
  const float* ln2b =(const float*)d_in[12];
  const float* pw3w =(const float*)d_in[13];
  const float* pw3b =(const float*)d_in[14];
  const float* pw4w =(const float*)d_in[15];
  const float* pw4b =(const float*)d_in[16];
  const float* beta1=(const float*)d_in[17];
  const float* beta2=(const float*)d_in[18];
  float* out=(float*)d_out;

  int smem7=128*72*2+128*136*2; // 53248 bytes
  cudaFuncSetAttribute(k7, cudaFuncAttributeMaxDynamicSharedMemorySize, smem7);

  dim3 g(256,8);
  k1 <<<512,256>>>(x);
  k2 <<<8,128>>>(ln1w,ln1b,pw1w,pw1b,pw4w);
  k3a<<<g,256>>>(x);
  k3b<<<g,256>>>(dww,dwb);
  k4 <<<8,64>>>(scaw,scab,pw2w);
  k5 <<<g,256>>>(x,pw2b,beta1,out);
  k6 <<<8,128>>>(ln2w,ln2b,pw3w,pw3b);
  k7 <<<dim3(512,8),256,smem7>>>(pw4b,beta2,out);
}

// round 4
// speedup vs baseline: 1.4283x; 1.4283x over previous
#include <cuda_runtime.h>
#include <cuda_bf16.h>
#include <cstdint>

#define HW 65536
#define NB 8

// ---- scratch (__device__ globals; allocation is forbidden) ----
__device__ float g_sum[512], g_sq[512], g_pool[512], g_s2[512], g_q2[512];
__device__ float g_b1f[NB*128], g_b3f[NB*128];
__device__ __nv_bfloat16 g_w1f[NB*128*64], g_w3f[NB*128*64], g_w2f[NB*64*64], g_w4h[64*64];
__device__ __nv_bfloat16 g_y[(size_t)NB*64*HW];    // gate output (64 MB)

__device__ __forceinline__ float warpsum(float v){
#pragma unroll
  for(int o=16;o>0;o>>=1) v += __shfl_down_sync(0xffffffffu, v, o);
  return v;
}

__device__ __forceinline__ void mma_bf16(float& d0,float& d1,float& d2,float& d3,
    uint32_t a0,uint32_t a1,uint32_t a2,uint32_t a3,uint32_t b0,uint32_t b1){
  asm volatile("mma.sync.aligned.m16n8k16.row.col.f32.bf16.bf16.f32 "
    "{%0,%1,%2,%3},{%4,%5,%6,%7},{%8,%9},{%0,%1,%2,%3};"
    : "+f"(d0),"+f"(d1),"+f"(d2),"+f"(d3)
    : "r"(a0),"r"(a1),"r"(a2),"r"(a3),"r"(b0),"r"(b1));
}

// load A fragments (4 k-steps) from row-major bf16 [rows][64]
__device__ __forceinline__ void loadA(uint32_t A[4][4], const __nv_bfloat16* wf,
                                      int m0,int grp,int t4){
#pragma unroll
  for(int k=0;k<4;k++){
    int c0=k*16+2*t4;
    A[k][0]=*(const uint32_t*)(wf+(m0+grp)*64+c0);
    A[k][1]=*(const uint32_t*)(wf+(m0+grp+8)*64+c0);
    A[k][2]=*(const uint32_t*)(wf+(m0+grp)*64+c0+8);
    A[k][3]=*(const uint32_t*)(wf+(m0+grp+8)*64+c0+8);
  }
}

// ---------------- K1: per-(n,c) sum / sumsq of x ----------------
__global__ __launch_bounds__(256) void k1(const float* __restrict__ x){
  int nc=blockIdx.x, tid=threadIdx.x;
  const float4* p=(const float4*)(x+(size_t)nc*HW);
  float s=0.f,q=0.f;
  for(int i=tid;i<HW/4;i+=256){
    float4 v=p[i];
    s+=(v.x+v.y)+(v.z+v.w);
    q+=v.x*v.x+v.y*v.y+v.z*v.z+v.w*v.w;
  }
  s=warpsum(s); q=warpsum(q);
  __shared__ float rs[8],rq[8];
  if((tid&31)==0){rs[tid>>5]=s;rq[tid>>5]=q;}
  __syncthreads();
  if(tid==0){
    float S=0,Q=0;
#pragma unroll
    for(int i=0;i<8;i++){S+=rs[i];Q+=rq[i];}
    g_sum[nc]=S; g_sq[nc]=Q;
  }
}

// ---------------- K2: fold ln1 into pw1; convert pw4; zero pool ----------------
__global__ void k2(const float* __restrict__ ln1w,const float* __restrict__ ln1b,
                   const float* __restrict__ pw1w,const float* __restrict__ pw1b,
                   const float* __restrict__ pw4w){
  int n=blockIdx.x, o=threadIdx.x; // 128 threads
  __shared__ float a[64], cc[64];
  if(o<64){
    float mean=g_sum[n*64+o]*(1.f/HW);
    float var =g_sq[n*64+o]*(1.f/HW)-mean*mean;
    float ai=ln1w[o]*rsqrtf(var+1e-6f);
    a[o]=ai; cc[o]=ln1b[o]-mean*ai;
    g_pool[n*64+o]=0.f;
  }
  __syncthreads();
  float bacc=pw1b[o];
#pragma unroll 8
  for(int c=0;c<64;c++){
    float w=pw1w[o*64+c];
    bacc+=w*cc[c];
    g_w1f[(n*128+o)*64+c]=__float2bfloat16(w*a[c]);
  }
  g_b1f[n*128+o]=bacc;
  if(n==0&&o<64){
    for(int c=0;c<64;c++) g_w4h[o*64+c]=__float2bfloat16(pw4w[o*64+c]);
  }
}

// ---------------- K3 (fused): pw1 GEMM + depthwise3x3 + gate + pool ----------------
// Tile: 8 rows x 32 cols output; halo 10x34 = 340 px (344 padded).
// smem: ts (64 pairs x 344 px, bf16x2 word = (c, c+64)) + xs chunk + dw weights.
#define TS_WORDS (64*344)
#define K3_SMEM (TS_WORDS*4 + 64*72*2 + 64*9*8 + 64*8)   // 102400 B

__device__ __forceinline__ bool pvalid(int p,int h0,int w0){
  int pr=p/34, pc=p-pr*34;
  int hh=h0-1+pr, wn=w0-1+pc;
  return ((unsigned)hh<256u)&&((unsigned)wn<256u);
}

__global__ __launch_bounds__(256) void k3(const float* __restrict__ x,
                                          const float* __restrict__ dww,
                                          const float* __restrict__ dwb){
  extern __shared__ char sm[];
  uint32_t* ts = (uint32_t*)sm;                                  // 88064 B
  __nv_bfloat16* xs = (__nv_bfloat16*)(sm + TS_WORDS*4);         // 9216 B
  float2* wsm = (float2*)(sm + TS_WORDS*4 + 64*72*2);            // 4608 B
  float2* bsm = (float2*)(sm + TS_WORDS*4 + 64*72*2 + 64*9*8);   // 512 B

  int wblk=blockIdx.x, hblk=blockIdx.y, n=blockIdx.z, tid=threadIdx.x;
  int h0=hblk*8, w0=wblk*32;
  int wid=tid>>5, lane=tid&31, grp=lane>>2, t4=lane&3, m0=wid*16;

  if(tid<64){
#pragma unroll
    for(int j=0;j<9;j++) wsm[tid*9+j]=make_float2(dww[tid*9+j], dww[(tid+64)*9+j]);
    bsm[tid]=make_float2(dwb[tid], dwb[tid+64]);
  }

  // A fragments + biases (same across chunks)
  const __nv_bfloat16* wf=g_w1f+(size_t)n*128*64;
  uint32_t A[4][4]; loadA(A,wf,m0,grp,t4);
  int mA=m0+grp, mB=m0+grp+8;
  float bv0=g_b1f[n*128+mA], bv8=g_b1f[n*128+mB];
  __nv_bfloat16* tsh=(__nv_bfloat16*)ts;
  const int iA0=(mA&63)*688+(mA>>6), iB0=(mB&63)*688+(mB>>6);

  // ---- phase 1: chunks of 64 px: load x halo -> bf16 xs, mma -> ts ----
  for(int chk=0;chk<6;chk++){
    int pbase=chk*64;
    __syncthreads();
    for(int i=tid;i<4096;i+=256){
      int pl=i&63, c=i>>6;
      int p=pbase+pl;
      int pr=p/34, pc=p-pr*34;
      int hh=h0-1+pr, wn=w0-1+pc;
      float v=0.f;
      if(p<344 && (unsigned)hh<256u && (unsigned)wn<256u)
        v=x[(size_t)(n*64+c)*HW + hh*256 + wn];
      xs[pl*72+c]=__float2bfloat16(v);
    }
    __syncthreads();
#pragma unroll
    for(int g=0;g<8;g++){
      int p0=g*8;
      const __nv_bfloat16* bs=xs+(p0+grp)*72+2*t4;
      float d0=0,d1=0,d2=0,d3=0;
#pragma unroll
      for(int k=0;k<4;k++){
        uint32_t b0=*(const uint32_t*)(bs+k*16), b1=*(const uint32_t*)(bs+k*16+8);
        mma_bf16(d0,d1,d2,d3,A[k][0],A[k][1],A[k][2],A[k][3],b0,b1);
      }
      int px=pbase+p0+2*t4;
      if(px<344){
        bool vA=pvalid(px,h0,w0), vB=pvalid(px+1,h0,w0);
        tsh[iA0+px*2]    =__float2bfloat16(vA?(d0+bv0):0.f);
        tsh[iA0+px*2+2]  =__float2bfloat16(vB?(d1+bv0):0.f);
        tsh[iB0+px*2]    =__float2bfloat16(vA?(d2+bv8):0.f);
        tsh[iB0+px*2+2]  =__float2bfloat16(vB?(d3+bv8):0.f);
      }
    }
  }
  __syncthreads();

  // ---- phase 2: depthwise 3x3 + gate + pool; warp wid owns pairs wid*8..+7 ----
  __nv_bfloat16* yb=g_y+(size_t)n*64*HW;
  for(int j=0;j<8;j++){
    int cp=wid*8+j;
    const uint32_t* tp=ts+cp*344;
    float2 wz[9];
#pragma unroll
    for(int q=0;q<9;q++) wz[q]=wsm[cp*9+q];
    float2 bz=bsm[cp];
    float2 r0[3],r1[3],r2[3];
#pragma unroll
    for(int k=0;k<3;k++){
      r0[k]=__bfloat1622float2(*(const __nv_bfloat162*)&tp[lane+k]);
      r1[k]=__bfloat1622float2(*(const __nv_bfloat162*)&tp[34+lane+k]);
    }
    float psum=0.f;
#pragma unroll
    for(int r=0;r<8;r++){
#pragma unroll
      for(int k=0;k<3;k++)
        r2[k]=__bfloat1622float2(*(const __nv_bfloat162*)&tp[(r+2)*34+lane+k]);
      float ax=bz.x, ay=bz.y;
#pragma unroll
      for(int k=0;k<3;k++){
        ax=fmaf(wz[k].x,  r0[k].x,ax); ay=fmaf(wz[k].y,  r0[k].y,ay);
        ax=fmaf(wz[3+k].x,r1[k].x,ax); ay=fmaf(wz[3+k].y,r1[k].y,ay);
        ax=fmaf(wz[6+k].x,r2[k].x,ax); ay=fmaf(wz[6+k].y,r2[k].y,ay);
      }
      float gv=ax*ay;
      yb[(size_t)cp*HW+(h0+r)*256+w0+lane]=__float2bfloat16(gv);
      psum+=gv;
#pragma unroll
      for(int k=0;k<3;k++){ r0[k]=r1[k]; r1[k]=r2[k]; }
    }
    psum=warpsum(psum);
    if(lane==0) atomicAdd(&g_pool[n*64+cp],psum);
  }
}

// ---------------- K4: SCA fold into pw2; zero ln2 stats ----------------
__global__ void k4(const float* __restrict__ scaw,const float* __restrict__ scab,
                   const float* __restrict__ pw2w){
  int n=blockIdx.x, o=threadIdx.x; // 64 threads
  __shared__ float v[64];
  float s=scab[o];
  for(int c=0;c<64;c++) s+=scaw[o*64+c]*(g_pool[n*64+c]*(1.f/HW));
  v[o]=1.f/(1.f+expf(-s));
  g_s2[n*64+o]=0.f; g_q2[n*64+o]=0.f;
  __syncthreads();
  for(int c=0;c<64;c++) g_w2f[(n*64+o)*64+c]=__float2bfloat16(pw2w[o*64+c]*v[c]);
}

// ---------------- K5: pw2 GEMM + residual1 + ln2 stats partials ----------------
__global__ __launch_bounds__(256) void k5(const float* __restrict__ x,
                                          const float* __restrict__ pw2b,
                                          const float* __restrict__ beta1,
                                          float* __restrict__ out){
  int row=blockIdx.x, n=blockIdx.y, tid=threadIdx.x;
  __shared__ __nv_bfloat16 xs[256*72];
  __shared__ float ss[64], sq[64];
  if(tid<64){ss[tid]=0.f;sq[tid]=0.f;}
  const __nv_bfloat16* yp=g_y+(size_t)n*64*HW+row*256;
  for(int i=tid;i<64*256;i+=256){int c=i>>8,p=i&255; xs[p*72+c]=yp[(size_t)c*HW+p];}
  __syncthreads();
  int wid=tid>>5, lane=tid&31, grp=lane>>2, t4=lane&3;
  int m0=(wid&3)*16, ph=(wid>>2)*128;
  const __nv_bfloat16* wf=g_w2f+n*64*64;
  uint32_t A[4][4]; loadA(A,wf,m0,grp,t4);
  int cA=m0+grp, cB=m0+grp+8;
  float biA=pw2b[cA],biB=pw2b[cB],beA=beta1[cA],beB=beta1[cB];
  const float* xpA=x+(size_t)(n*64+cA)*HW+row*256;
  const float* xpB=x+(size_t)(n*64+cB)*HW+row*256;
  float* opA=out+(size_t)(n*64+cA)*HW+row*256;
  float* opB=out+(size_t)(n*64+cB)*HW+row*256;
  float sA=0,qA=0,sB=0,qB=0;
  for(int nt=0;nt<16;nt++){
    int p0=ph+nt*8;
    const __nv_bfloat16* bs=xs+(p0+grp)*72+2*t4;
    float d0=0,d1=0,d2=0,d3=0;
#pragma unroll
    for(int k=0;k<4;k++){
      uint32_t b0=*(const uint32_t*)(bs+k*16), b1=*(const uint32_t*)(bs+k*16+8);
      mma_bf16(d0,d1,d2,d3,A[k][0],A[k][1],A[k][2],A[k][3],b0,b1);
    }
    int px=p0+2*t4;
    float2 xa=*(const float2*)(xpA+px), xb=*(const float2*)(xpB+px);
    float o0=xa.x+beA*(d0+biA), o1=xa.y+beA*(d1+biA);
    float o2=xb.x+beB*(d2+biB), o3=xb.y+beB*(d3+biB);
    *(float2*)(opA+px)=make_float2(o0,o1);
    *(float2*)(opB+px)=make_float2(o2,o3);
    sA+=o0+o1; qA+=o0*o0+o1*o1; sB+=o2+o3; qB+=o2*o2+o3*o3;
  }
  sA+=__shfl_down_sync(0xffffffffu,sA,2); sA+=__shfl_down_sync(0xffffffffu,sA,1);
  qA+=__shfl_down_sync(0xffffffffu,qA,2); qA+=__shfl_down_sync(0xffffffffu,qA,1);
  sB+=__shfl_down_sync(0xffffffffu,sB,2); sB+=__shfl_down_sync(0xffffffffu,sB,1);
  qB+=__shfl_down_sync(0xffffffffu,qB,2); qB+=__shfl_down_sync(0xffffffffu,qB,1);
  if(t4==0){
    atomicAdd(&ss[cA],sA); atomicAdd(&sq[cA],qA);
    atomicAdd(&ss[cB],sB); atomicAdd(&sq[cB],qB);
  }
  __syncthreads();
  if(tid<64){atomicAdd(&g_s2[n*64+tid],ss[tid]); atomicAdd(&g_q2[n*64+tid],sq[tid]);}
}

// ---------------- K6: fold ln2 into pw3 ----------------
__global__ void k6(const float* __restrict__ ln2w,const float* __restrict__ ln2b,
                   const float* __restrict__ pw3w,const float* __restrict__ pw3b){
  int n=blockIdx.x, o=threadIdx.x; // 128
  __shared__ float a[64], cc[64];
  if(o<64){
    float mean=g_s2[n*64+o]*(1.f/HW);
    float var =g_q2[n*64+o]*(1.f/HW)-mean*mean;
    float ai=ln2w[o]*rsqrtf(var+1e-6f);
    a[o]=ai; cc[o]=ln2b[o]-mean*ai;
  }
  __syncthreads();
  float bacc=pw3b[o];
#pragma unroll 8
  for(int c=0;c<64;c++){
    float w=pw3w[o*64+c];
    bacc+=w*cc[c];
    g_w3f[(n*128+o)*64+c]=__float2bfloat16(w*a[c]);
  }
  g_b3f[n*128+o]=bacc;
}

// ---------------- K7: pw3 + gate + pw4 + residual2 (in-place on d_out) ----------------
__global__ __launch_bounds__(256) void k7(const float* __restrict__ pw4b,
                                          const float* __restrict__ beta2,
                                          float* __restrict__ out){
  extern __shared__ __nv_bfloat16 sm7[];
  __nv_bfloat16* xs=sm7;            // [128][72]
  __nv_bfloat16* ts=sm7+128*72;     // [128][136]
  int blk=blockIdx.x, n=blockIdx.y, tid=threadIdx.x;
  int base=blk*128;
  const float* xp=out+(size_t)n*64*HW+base;
  for(int i=tid;i<64*128;i+=256){int c=i>>7,p=i&127; xs[p*72+c]=__float2bfloat16(xp[(size_t)c*HW+p]);}
  __syncthreads();
  int wid=tid>>5, lane=tid&31, grp=lane>>2, t4=lane&3;
  { // stage 1: t[128ch] = W3f @ x
    int m0=wid*16;
    const __nv_bfloat16* wf=g_w3f+(size_t)n*128*64;
    uint32_t A[4][4]; loadA(A,wf,m0,grp,t4);
    float bv0=g_b3f[n*128+m0+grp], bv8=g_b3f[n*128+m0+grp+8];
    for(int nt=0;nt<16;nt++){
      int p0=nt*8;
      const __nv_bfloat16* bs=xs+(p0+grp)*72+2*t4;
      float d0=0,d1=0,d2=0,d3=0;
#pragma unroll
      for(int k=0;k<4;k++){
        uint32_t b0=*(const uint32_t*)(bs+k*16), b1=*(const uint32_t*)(bs+k*16+8);
        mma_bf16(d0,d1,d2,d3,A[k][0],A[k][1],A[k][2],A[k][3],b0,b1);
      }
      int px=p0+2*t4;
      ts[px*136+m0+grp]      =__float2bfloat16(d0+bv0);
      ts[(px+1)*136+m0+grp]  =__float2bfloat16(d1+bv0);
      ts[px*136+m0+grp+8]    =__float2bfloat16(d2+bv8);
      ts[(px+1)*136+m0+grp+8]=__float2bfloat16(d3+bv8);
    }
  }
  __syncthreads();
  { // stage 2: z = W4 @ (t[0:64]*t[64:128]); out = x + beta2*(z+b4)
    int m0=(wid&3)*16, ph=(wid>>2)*64;
    uint32_t A[4][4]; loadA(A,g_w4h,m0,grp,t4);
    int cA=m0+grp, cB=m0+grp+8;
    float biA=pw4b[cA],biB=pw4b[cB],beA=beta2[cA],beB=beta2[cB];
    const float* rpA=out+(size_t)(n*64+cA)*HW+base;
    const float* rpB=out+(size_t)(n*64+cB)*HW+base;
    float* opA=out+(size_t)(n*64+cA)*HW+base;
    float* opB=out+(size_t)(n*64+cB)*HW+base;
    for(int nt=0;nt<8;nt++){
      int p0=ph+nt*8;
      const __nv_bfloat16* bs=ts+(p0+grp)*136+2*t4;
      float d0=0,d1=0,d2=0,d3=0;
#pragma unroll
      for(int k=0;k<4;k++){
        __nv_bfloat162 u1=*(const __nv_bfloat162*)(bs+k*16);
        __nv_bfloat162 u2=*(const __nv_bfloat162*)(bs+k*16+64);
        __nv_bfloat162 v1=*(const __nv_bfloat162*)(bs+k*16+8);
        __nv_bfloat162 v2=*(const __nv_bfloat162*)(bs+k*16+72);
        __nv_bfloat162 bb0=__hmul2(u1,u2), bb1=__hmul2(v1,v2);
        mma_bf16(d0,d1,d2,d3,A[k][0],A[k][1],A[k][2],A[k][3],
                 *(uint32_t*)&bb0,*(uint32_t*)&bb1);
      }
      int px=p0+2*t4;
      float2 xa=*(const float2*)(rpA+px), xb=*(const float2*)(rpB+px);
      float o0=xa.x+beA*(d0+biA), o1=xa.y+beA*(d1+biA);
      float o2=xb.x+beB*(d2+biB), o3=xb.y+beB*(d3+biB);
      *(float2*)(opA+px)=make_float2(o0,o1);
      *(float2*)(opB+px)=make_float2(o2,o3);
    }
  }
}

extern "C" void kernel_launch(void* const* d_in, const int* in_sizes, int n_in,
                              void* d_out, int out_size){
  const float* x    =(const float*)d_in[0];
  const float* ln1w =(const float*)d_in[1];
  const float* ln1b =(const float*)d_in[2];
  const float* pw1w =(const float*)d_in[3];
  const float* pw1b =(const float*)d_in[4];
  const float* dww  =(const float*)d_in[5];
  const float* dwb  =(const float*)d_in[6];
  const float* scaw =(const float*)d_in[7];
  const float* scab =(const float*)d_in[8];
  const float* pw2w =(const float*)d_in[9];
  const float* pw2b =(const float*)d_in[10];
  const float* ln2w =(const float*)d_in[11];
  const float* ln2b =(const float*)d_in[12];
  const float* pw3w =(const float*)d_in[13];
  const float* pw3b =(const float*)d_in[14];
  const float* pw4w =(const float*)d_in[15];
  const float* pw4b =(const float*)d_in[16];
  const float* beta1=(const float*)d_in[17];
  const float* beta2=(const float*)d_in[18];
  float* out=(float*)d_out;

  cudaFuncSetAttribute(k3, cudaFuncAttributeMaxDynamicSharedMemorySize, K3_SMEM);
  int smem7=128*72*2+128*136*2; // 53248 bytes
  cudaFuncSetAttribute(k7, cudaFuncAttributeMaxDynamicSharedMemorySize, smem7);

  k1 <<<512,256>>>(x);
  k2 <<<8,128>>>(ln1w,ln1b,pw1w,pw1b,pw4w);
  k3 <<<dim3(8,32,8),256,K3_SMEM>>>(x,dww,dwb);
  k4 <<<8,64>>>(scaw,scab,pw2w);
  k5 <<<dim3(256,8),256>>>(x,pw2b,beta1,out);
  k6 <<<8,128>>>(ln2w,ln2b,pw3w,pw3b);
  k7 <<<dim3(512,8),256,smem7>>>(pw4b,beta2,out);
}

// round 5
// speedup vs baseline: 1.5849x; 1.1096x over previous
#include <cuda_runtime.h>
#include <cuda_bf16.h>
#include <cstdint>

#define HW 65536
#define NB 8

// ---- scratch (__device__ globals; allocation is forbidden) ----
__device__ float g_sum[512], g_sq[512], g_pool[512], g_s2[512], g_q2[512];
__device__ float g_b1f[NB*128], g_b3f[NB*128];
__device__ __nv_bfloat16 g_w1f[NB*128*64], g_w3f[NB*128*64], g_w2f[NB*64*64], g_w4h[64*64];
__device__ __nv_bfloat16 g_y[(size_t)NB*64*HW];    // gate output (64 MB)
__device__ int g_cnt1[NB], g_cnt3[NB], g_cnt5[NB]; // zero-init; self-reset each use

__device__ __forceinline__ float warpsum(float v){
#pragma unroll
  for(int o=16;o>0;o>>=1) v += __shfl_down_sync(0xffffffffu, v, o);
  return v;
}

__device__ __forceinline__ void mma_bf16(float& d0,float& d1,float& d2,float& d3,
    uint32_t a0,uint32_t a1,uint32_t a2,uint32_t a3,uint32_t b0,uint32_t b1){
  asm volatile("mma.sync.aligned.m16n8k16.row.col.f32.bf16.bf16.f32 "
    "{%0,%1,%2,%3},{%4,%5,%6,%7},{%8,%9},{%0,%1,%2,%3};"
    : "+f"(d0),"+f"(d1),"+f"(d2),"+f"(d3)
    : "r"(a0),"r"(a1),"r"(a2),"r"(a3),"r"(b0),"r"(b1));
}

// load A fragments (4 k-steps) from row-major bf16 [rows][64]
__device__ __forceinline__ void loadA(uint32_t A[4][4], const __nv_bfloat16* wf,
                                      int m0,int grp,int t4){
#pragma unroll
  for(int k=0;k<4;k++){
    int c0=k*16+2*t4;
    A[k][0]=*(const uint32_t*)(wf+(m0+grp)*64+c0);
    A[k][1]=*(const uint32_t*)(wf+(m0+grp+8)*64+c0);
    A[k][2]=*(const uint32_t*)(wf+(m0+grp)*64+c0+8);
    A[k][3]=*(const uint32_t*)(wf+(m0+grp+8)*64+c0+8);
  }
}

// ---------------- K1: stats of x + (last block per n) ln1->pw1 fold ----------------
__global__ __launch_bounds__(256) void k1(const float* __restrict__ x,
                                          const float* __restrict__ ln1w,const float* __restrict__ ln1b,
                                          const float* __restrict__ pw1w,const float* __restrict__ pw1b,
                                          const float* __restrict__ pw4w){
  int nc=blockIdx.x, n=nc>>6, tid=threadIdx.x;
  const float4* p=(const float4*)(x+(size_t)nc*HW);
  float s=0.f,q=0.f;
  for(int i=tid;i<HW/4;i+=256){
    float4 v=p[i];
    s+=(v.x+v.y)+(v.z+v.w);
    q+=v.x*v.x+v.y*v.y+v.z*v.z+v.w*v.w;
  }
  s=warpsum(s); q=warpsum(q);
  __shared__ float rs[8],rq[8];
  if((tid&31)==0){rs[tid>>5]=s;rq[tid>>5]=q;}
  __syncthreads();
  __shared__ int lastf;
  if(tid==0){
    float S=0,Q=0;
#pragma unroll
    for(int i=0;i<8;i++){S+=rs[i];Q+=rq[i];}
    g_sum[nc]=S; g_sq[nc]=Q;
    __threadfence();
    lastf=(atomicAdd(&g_cnt1[n],1)==63);
  }
  __syncthreads();
  if(!lastf) return;
  // ---- tail: fold ln1 into pw1 for this n; convert pw4 (n==0); zero pool ----
  if(tid==0){ g_cnt1[n]=0; __threadfence(); }
  __shared__ float a[64], cc[64];
  if(tid<64){
    float mean=g_sum[n*64+tid]*(1.f/HW);
    float var =g_sq[n*64+tid]*(1.f/HW)-mean*mean;
    float ai=ln1w[tid]*rsqrtf(var+1e-6f);
    a[tid]=ai; cc[tid]=ln1b[tid]-mean*ai;
    g_pool[n*64+tid]=0.f;
  }
  __syncthreads();
  if(tid<128){
    int o=tid;
    float bacc=pw1b[o];
#pragma unroll 8
    for(int c=0;c<64;c++){
      float w=pw1w[o*64+c];
      bacc+=w*cc[c];
      g_w1f[(n*128+o)*64+c]=__float2bfloat16(w*a[c]);
    }
    g_b1f[n*128+o]=bacc;
  } else if(n==0 && tid<192){
    int o=tid-128;
    for(int c=0;c<64;c++) g_w4h[o*64+c]=__float2bfloat16(pw4w[o*64+c]);
  }
}

// ---------------- K3 (fused): pw1 GEMM + depthwise3x3 + gate + pool + SCA fold ----------------
#define TS_WORDS (64*344)
#define K3_SMEM (TS_WORDS*4 + 64*72*2 + 64*9*8 + 64*8)   // 102400 B

__device__ __forceinline__ bool pvalid(int p,int h0,int w0){
  int pr=p/34, pc=p-pr*34;
  int hh=h0-1+pr, wn=w0-1+pc;
  return ((unsigned)hh<256u)&&((unsigned)wn<256u);
}

__global__ __launch_bounds__(256) void k3(const float* __restrict__ x,
                                          const float* __restrict__ dww,
                                          const float* __restrict__ dwb,
                                          const float* __restrict__ scaw,
                                          const float* __restrict__ scab,
                                          const float* __restrict__ pw2w){
  extern __shared__ char sm[];
  uint32_t* ts = (uint32_t*)sm;                                  // 88064 B
  __nv_bfloat16* xs = (__nv_bfloat16*)(sm + TS_WORDS*4);         // 9216 B
  float2* wsm = (float2*)(sm + TS_WORDS*4 + 64*72*2);            // 4608 B
  float2* bsm = (float2*)(sm + TS_WORDS*4 + 64*72*2 + 64*9*8);   // 512 B

  int wblk=blockIdx.x, hblk=blockIdx.y, n=blockIdx.z, tid=threadIdx.x;
  int h0=hblk*8, w0=wblk*32;
  int wid=tid>>5, lane=tid&31, grp=lane>>2, t4=lane&3, m0=wid*16;

  if(tid<64){
#pragma unroll
    for(int j=0;j<9;j++) wsm[tid*9+j]=make_float2(dww[tid*9+j], dww[(tid+64)*9+j]);
    bsm[tid]=make_float2(dwb[tid], dwb[tid+64]);
  }

  const __nv_bfloat16* wf=g_w1f+(size_t)n*128*64;
  uint32_t A[4][4]; loadA(A,wf,m0,grp,t4);
  int mA=m0+grp, mB=m0+grp+8;
  float bv0=g_b1f[n*128+mA], bv8=g_b1f[n*128+mB];
  __nv_bfloat16* tsh=(__nv_bfloat16*)ts;
  const int iA0=(mA&63)*688+(mA>>6), iB0=(mB&63)*688+(mB>>6);

  // ---- phase 1: software-pipelined chunks of 64 px ----
  const int pl=tid&63, c0=tid>>6;   // this thread: pixel slot pl, channels c0+4j
  const float* xb=x+(size_t)n*64*HW;
  float v[16];
  // prologue: load chunk 0
  {
    int p=pl;
    int pr=p/34, pc=p-pr*34;
    int hh=h0-1+pr, wn=w0-1+pc;
    bool ok=((unsigned)hh<256u)&&((unsigned)wn<256u);
    const float* px=xb+(size_t)c0*HW+hh*256+wn;
#pragma unroll
    for(int j=0;j<16;j++) v[j]= ok ? px[(size_t)(4*j)*HW] : 0.f;
  }
  for(int chk=0;chk<6;chk++){
    if(chk) __syncthreads();                  // prev mma done reading xs
#pragma unroll
    for(int j=0;j<16;j++) xs[pl*72+c0+4*j]=__float2bfloat16(v[j]);
    __syncthreads();
    if(chk<5){                                // prefetch next chunk (overlaps mma)
      int p=(chk+1)*64+pl;
      int pr=p/34, pc=p-pr*34;
      int hh=h0-1+pr, wn=w0-1+pc;
      bool ok=(p<344)&&((unsigned)hh<256u)&&((unsigned)wn<256u);
      const float* px=xb+(size_t)c0*HW+hh*256+wn;
#pragma unroll
      for(int j=0;j<16;j++) v[j]= ok ? px[(size_t)(4*j)*HW] : 0.f;
    }
    int pbase=chk*64;
#pragma unroll
    for(int g=0;g<8;g++){
      int p0=g*8;
      const __nv_bfloat16* bs=xs+(p0+grp)*72+2*t4;
      float d0=0,d1=0,d2=0,d3=0;
#pragma unroll
      for(int k=0;k<4;k++){
        uint32_t b0=*(const uint32_t*)(bs+k*16), b1=*(const uint32_t*)(bs+k*16+8);
        mma_bf16(d0,d1,d2,d3,A[k][0],A[k][1],A[k][2],A[k][3],b0,b1);
      }
      int px=pbase+p0+2*t4;
      if(px<344){
        bool vA=pvalid(px,h0,w0), vB=pvalid(px+1,h0,w0);
        tsh[iA0+px*2]    =__float2bfloat16(vA?(d0+bv0):0.f);
        tsh[iA0+px*2+2]  =__float2bfloat16(vB?(d1+bv0):0.f);
        tsh[iB0+px*2]    =__float2bfloat16(vA?(d2+bv8):0.f);
        tsh[iB0+px*2+2]  =__float2bfloat16(vB?(d3+bv8):0.f);
      }
    }
  }
  __syncthreads();

  // ---- phase 2: depthwise 3x3 + gate + pool ----
  __nv_bfloat16* yb=g_y+(size_t)n*64*HW;
  float psumTot[8];
  for(int j=0;j<8;j++){
    int cp=wid*8+j;
    const uint32_t* tp=ts+cp*344;
    float2 wz[9];
#pragma unroll
    for(int q=0;q<9;q++) wz[q]=wsm[cp*9+q];
    float2 bz=bsm[cp];
    float2 r0[3],r1[3],r2[3];
#pragma unroll
    for(int k=0;k<3;k++){
      r0[k]=__bfloat1622float2(*(const __nv_bfloat162*)&tp[lane+k]);
      r1[k]=__bfloat1622float2(*(const __nv_bfloat162*)&tp[34+lane+k]);
    }
    float psum=0.f;
#pragma unroll
    for(int r=0;r<8;r++){
#pragma unroll
      for(int k=0;k<3;k++)
        r2[k]=__bfloat1622float2(*(const __nv_bfloat162*)&tp[(r+2)*34+lane+k]);
      float ax=bz.x, ay=bz.y;
#pragma unroll
      for(int k=0;k<3;k++){
        ax=fmaf(wz[k].x,  r0[k].x,ax); ay=fmaf(wz[k].y,  r0[k].y,ay);
        ax=fmaf(wz[3+k].x,r1[k].x,ax); ay=fmaf(wz[3+k].y,r1[k].y,ay);
        ax=fmaf(wz[6+k].x,r2[k].x,ax); ay=fmaf(wz[6+k].y,r2[k].y,ay);
      }
      float gv=ax*ay;
      yb[(size_t)cp*HW+(h0+r)*256+w0+lane]=__float2bfloat16(gv);
      psum+=gv;
#pragma unroll
      for(int k=0;k<3;k++){ r0[k]=r1[k]; r1[k]=r2[k]; }
    }
    psumTot[j]=warpsum(psum);
  }
  if(lane==0){
#pragma unroll
    for(int j=0;j<8;j++) atomicAdd(&g_pool[n*64+wid*8+j],psumTot[j]);
    __threadfence();
  }
  __syncthreads();
  // ---- tail: last block per n does SCA fold into pw2, zeroes ln2 stats ----
  __shared__ int last3;
  if(tid==0) last3=(atomicAdd(&g_cnt3[n],1)==255);
  __syncthreads();
  if(!last3) return;
  if(tid==0) g_cnt3[n]=0;
  __shared__ float vsig[64];
  if(tid<64){
    float s=scab[tid];
    for(int c=0;c<64;c++) s+=scaw[tid*64+c]*(g_pool[n*64+c]*(1.f/HW));
    vsig[tid]=1.f/(1.f+expf(-s));
    g_s2[n*64+tid]=0.f; g_q2[n*64+tid]=0.f;
  }
  __syncthreads();
  for(int i=tid;i<4096;i+=256) g_w2f[n*4096+i]=__float2bfloat16(pw2w[i]*vsig[i&63]);
}

// ---------------- K5: pw2 GEMM + residual1 + ln2 stats + (last block) ln2->pw3 fold ----------------
__global__ __launch_bounds__(256) void k5(const float* __restrict__ x,
                                          const float* __restrict__ pw2b,
                                          const float* __restrict__ beta1,
                                          float* __restrict__ out,
                                          const float* __restrict__ ln2w,const float* __restrict__ ln2b,
                                          const float* __restrict__ pw3w,const float* __restrict__ pw3b){
  int row=blockIdx.x, n=blockIdx.y, tid=threadIdx.x;
  __shared__ __nv_bfloat16 xs[256*72];
  __shared__ float ss[64], sq[64];
  if(tid<64){ss[tid]=0.f;sq[tid]=0.f;}
  const __nv_bfloat16* yp=g_y+(size_t)n*64*HW+row*256;
  for(int i=tid;i<64*256;i+=256){int c=i>>8,p=i&255; xs[p*72+c]=yp[(size_t)c*HW+p];}
  __syncthreads();
  int wid=tid>>5, lane=tid&31, grp=lane>>2, t4=lane&3;
  int m0=(wid&3)*16, ph=(wid>>2)*128;
  const __nv_bfloat16* wf=g_w2f+n*64*64;
  uint32_t A[4][4]; loadA(A,wf,m0,grp,t4);
  int cA=m0+grp, cB=m0+grp+8;
  float biA=pw2b[cA],biB=pw2b[cB],beA=beta1[cA],beB=beta1[cB];
  const float* xpA=x+(size_t)(n*64+cA)*HW+row*256;
  const float* xpB=x+(size_t)(n*64+cB)*HW+row*256;
  float* opA=out+(size_t)(n*64+cA)*HW+row*256;
  float* opB=out+(size_t)(n*64+cB)*HW+row*256;
  float sA=0,qA=0,sB=0,qB=0;
  for(int nt=0;nt<16;nt++){
    int p0=ph+nt*8;
    const __nv_bfloat16* bs=xs+(p0+grp)*72+2*t4;
    float d0=0,d1=0,d2=0,d3=0;
#pragma unroll
    for(int k=0;k<4;k++){
      uint32_t b0=*(const uint32_t*)(bs+k*16), b1=*(const uint32_t*)(bs+k*16+8);
      mma_bf16(d0,d1,d2,d3,A[k][0],A[k][1],A[k][2],A[k][3],b0,b1);
    }
    int px=p0+2*t4;
    float2 xa=*(const float2*)(xpA+px), xb=*(const float2*)(xpB+px);
    float o0=xa.x+beA*(d0+biA), o1=xa.y+beA*(d1+biA);
    float o2=xb.x+beB*(d2+biB), o3=xb.y+beB*(d3+biB);
    *(float2*)(opA+px)=make_float2(o0,o1);
    *(float2*)(opB+px)=make_float2(o2,o3);
    sA+=o0+o1; qA+=o0*o0+o1*o1; sB+=o2+o3; qB+=o2*o2+o3*o3;
  }
  sA+=__shfl_down_sync(0xffffffffu,sA,2); sA+=__shfl_down_sync(0xffffffffu,sA,1);
  qA+=__shfl_down_sync(0xffffffffu,qA,2); qA+=__shfl_down_sync(0xffffffffu,qA,1);
  sB+=__shfl_down_sync(0xffffffffu,sB,2); sB+=__shfl_down_sync(0xffffffffu,sB,1);
  qB+=__shfl_down_sync(0xffffffffu,qB,2); qB+=__shfl_down_sync(0xffffffffu,qB,1);
  if(t4==0){
    atomicAdd(&ss[cA],sA); atomicAdd(&sq[cA],qA);
    atomicAdd(&ss[cB],sB); atomicAdd(&sq[cB],qB);
  }
  __syncthreads();
  if(tid<64){
    atomicAdd(&g_s2[n*64+tid],ss[tid]); atomicAdd(&g_q2[n*64+tid],sq[tid]);
    __threadfence();
  }
  __syncthreads();
  // ---- tail: last block per n folds ln2 into pw3 ----
  __shared__ int last5;
  if(tid==0) last5=(atomicAdd(&g_cnt5[n],1)==255);
  __syncthreads();
  if(!last5) return;
  if(tid==0) g_cnt5[n]=0;
  __shared__ float a2[64], cc2[64];
  if(tid<64){
    float mean=g_s2[n*64+tid]*(1.f/HW);
    float var =g_q2[n*64+tid]*(1.f/HW)-mean*mean;
    float ai=ln2w[tid]*rsqrtf(var+1e-6f);
    a2[tid]=ai; cc2[tid]=ln2b[tid]-mean*ai;
  }
  __syncthreads();
  if(tid<128){
    int o=tid;
    float bacc=pw3b[o];
#pragma unroll 8
    for(int c=0;c<64;c++){
      float w=pw3w[o*64+c];
      bacc+=w*cc2[c];
      g_w3f[(n*128+o)*64+c]=__float2bfloat16(w*a2[c]);
    }
    g_b3f[n*128+o]=bacc;
  }
}

// ---------------- K7: pw3 + gate + pw4 + residual2 (in-place on d_out) ----------------
__global__ __launch_bounds__(256) void k7(const float* __restrict__ pw4b,
                                          const float* __restrict__ beta2,
                                          float* __restrict__ out){
  extern __shared__ __nv_bfloat16 sm7[];
  __nv_bfloat16* xs=sm7;            // [128][72]
  __nv_bfloat16* ts=sm7+128*72;     // [128][136]
  int blk=blockIdx.x, n=blockIdx.y, tid=threadIdx.x;
  int base=blk*128;
  const float* xp=out+(size_t)n*64*HW+base;
  for(int i=tid;i<64*128;i+=256){int c=i>>7,p=i&127; xs[p*72+c]=__float2bfloat16(xp[(size_t)c*HW+p]);}
  __syncthreads();
  int wid=tid>>5, lane=tid&31, grp=lane>>2, t4=lane&3;
  { // stage 1: t[128ch] = W3f @ x
    int m0=wid*16;
    const __nv_bfloat16* wf=g_w3f+(size_t)n*128*64;
    uint32_t A[4][4]; loadA(A,wf,m0,grp,t4);
    float bv0=g_b3f[n*128+m0+grp], bv8=g_b3f[n*128+m0+grp+8];
    for(int nt=0;nt<16;nt++){
      int p0=nt*8;
      const __nv_bfloat16* bs=xs+(p0+grp)*72+2*t4;
      float d0=0,d1=0,d2=0,d3=0;
#pragma unroll
      for(int k=0;k<4;k++){
        uint32_t b0=*(const uint32_t*)(bs+k*16), b1=*(const uint32_t*)(bs+k*16+8);
        mma_bf16(d0,d1,d2,d3,A[k][0],A[k][1],A[k][2],A[k][3],b0,b1);
      }
      int px=p0+2*t4;
      ts[px*136+m0+grp]      =__float2bfloat16(d0+bv0);
      ts[(px+1)*136+m0+grp]  =__float2bfloat16(d1+bv0);
      ts[px*136+m0+grp+8]    =__float2bfloat16(d2+bv8);
      ts[(px+1)*136+m0+grp+8]=__float2bfloat16(d3+bv8);
    }
  }
  __syncthreads();
  { // stage 2: z = W4 @ (t[0:64]*t[64:128]); out = x + beta2*(z+b4)
    int m0=(wid&3)*16, ph=(wid>>2)*64;
    uint32_t A[4][4]; loadA(A,g_w4h,m0,grp,t4);
    int cA=m0+grp, cB=m0+grp+8;
    float biA=pw4b[cA],biB=pw4b[cB],beA=beta2[cA],beB=beta2[cB];
    const float* rpA=out+(size_t)(n*64+cA)*HW+base;
    const float* rpB=out+(size_t)(n*64+cB)*HW+base;
    float* opA=out+(size_t)(n*64+cA)*HW+base;
    float* opB=out+(size_t)(n*64+cB)*HW+base;
    for(int nt=0;nt<8;nt++){
      int p0=ph+nt*8;
      const __nv_bfloat16* bs=ts+(p0+grp)*136+2*t4;
      float d0=0,d1=0,d2=0,d3=0;
#pragma unroll
      for(int k=0;k<4;k++){
        __nv_bfloat162 u1=*(const __nv_bfloat162*)(bs+k*16);
        __nv_bfloat162 u2=*(const __nv_bfloat162*)(bs+k*16+64);
        __nv_bfloat162 v1=*(const __nv_bfloat162*)(bs+k*16+8);
        __nv_bfloat162 v2=*(const __nv_bfloat162*)(bs+k*16+72);
        __nv_bfloat162 bb0=__hmul2(u1,u2), bb1=__hmul2(v1,v2);
        mma_bf16(d0,d1,d2,d3,A[k][0],A[k][1],A[k][2],A[k][3],
                 *(uint32_t*)&bb0,*(uint32_t*)&bb1);
      }
      int px=p0+2*t4;
      float2 xa=*(const float2*)(rpA+px), xb=*(const float2*)(rpB+px);
      float o0=xa.x+beA*(d0+biA), o1=xa.y+beA*(d1+biA);
      float o2=xb.x+beB*(d2+biB), o3=xb.y+beB*(d3+biB);
      *(float2*)(opA+px)=make_float2(o0,o1);
      *(float2*)(opB+px)=make_float2(o2,o3);
    }
  }
}

extern "C" void kernel_launch(void* const* d_in, const int* in_sizes, int n_in,
                              void* d_out, int out_size){
  const float* x    =(const float*)d_in[0];
  const float* ln1w =(const float*)d_in[1];
  const float* ln1b =(const float*)d_in[2];
  const float* pw1w =(const float*)d_in[3];
  const float* pw1b =(const float*)d_in[4];
  const float* dww  =(const float*)d_in[5];
  const float* dwb  =(const float*)d_in[6];
  const float* scaw =(const float*)d_in[7];
  const float* scab =(const float*)d_in[8];
  const float* pw2w =(const float*)d_in[9];
  const float* pw2b =(const float*)d_in[10];
  const float* ln2w =(const float*)d_in[11];
  const float* ln2b =(const float*)d_in[12];
  const float* pw3w =(const float*)d_in[13];
  const float* pw3b =(const float*)d_in[14];
  const float* pw4w =(const float*)d_in[15];
  const float* pw4b =(const float*)d_in[16];
  const float* beta1=(const float*)d_in[17];
  const float* beta2=(const float*)d_in[18];
  float* out=(float*)d_out;

  cudaFuncSetAttribute(k3, cudaFuncAttributeMaxDynamicSharedMemorySize, K3_SMEM);
  int smem7=128*72*2+128*136*2; // 53248 bytes
  cudaFuncSetAttribute(k7, cudaFuncAttributeMaxDynamicSharedMemorySize, smem7);

  k1 <<<512,256>>>(x,ln1w,ln1b,pw1w,pw1b,pw4w);
  k3 <<<dim3(8,32,8),256,K3_SMEM>>>(x,dww,dwb,scaw,scab,pw2w);
  k5 <<<dim3(256,8),256>>>(x,pw2b,beta1,out,ln2w,ln2b,pw3w,pw3b);
  k7 <<<dim3(512,8),256,smem7>>>(pw4b,beta2,out);
}